// round 16
// baseline (speedup 1.0000x reference)
#include <cuda_runtime.h>
#include <cstdint>

#define BB 2
#define SS 2048
#define DD 1024
#define HH 16
#define HD 64

// Scratch: g_Q [b,h][s][64]; g_K TRANSPOSED [b,h][d][s]; g_V [b,h][s][64]
// (V values pre-rounded to tf32 in proj — terminal path, bit-identical out).
__device__ float g_Q[BB*HH*SS*HD];
__device__ float g_K[BB*HH*SS*HD];
__device__ float g_V[BB*HH*SS*HD];

// ---------------------------------------------------------------------------
// Packed f32x2 helpers (exact IEEE fp32 per lane).
// ---------------------------------------------------------------------------
typedef unsigned long long u64cu;
union F4U2 { float4 f4; u64cu u2[2]; };

__device__ __forceinline__ u64cu dup2(float x) {
    u64cu r; asm("mov.b64 %0, {%1, %1};" : "=l"(r) : "f"(x)); return r;
}
__device__ __forceinline__ void fma2(u64cu& c, u64cu a, u64cu b) {
    asm("fma.rn.f32x2 %0, %1, %2, %0;" : "+l"(c) : "l"(a), "l"(b));
}
__device__ __forceinline__ float2 up2(u64cu v) {
    float2 f; asm("mov.b64 {%0, %1}, %2;" : "=f"(f.x), "=f"(f.y) : "l"(v));
    return f;
}

// ---------------------------------------------------------------------------
// tf32 mma.sync helpers (downstream-of-softmax paths only).
// ---------------------------------------------------------------------------
__device__ __forceinline__ uint32_t f2tf32(float x) {
    uint32_t r;
    asm("cvt.rna.tf32.f32 %0, %1;" : "=r"(r) : "f"(x));
    return r;
}
__device__ __forceinline__ void split_tf32(float v, float& hi, float& lo) {
    uint32_t hb;
    asm("cvt.rna.tf32.f32 %0, %1;" : "=r"(hb) : "f"(v));
    hi = __uint_as_float(hb);
    float r = v - hi;
    uint32_t lb;
    asm("cvt.rna.tf32.f32 %0, %1;" : "=r"(lb) : "f"(r));
    lo = __uint_as_float(lb);
}
__device__ __forceinline__ void mma8(float* c, const uint32_t* a, const uint32_t* bf) {
    asm volatile("mma.sync.aligned.m16n8k8.row.col.f32.tf32.tf32.f32 "
                 "{%0,%1,%2,%3}, {%4,%5,%6,%7}, {%8,%9}, {%0,%1,%2,%3};"
                 : "+f"(c[0]), "+f"(c[1]), "+f"(c[2]), "+f"(c[3])
                 : "r"(a[0]), "r"(a[1]), "r"(a[2]), "r"(a[3]),
                   "r"(bf[0]), "r"(bf[1]));
}

// cp.async (Ampere+ PTX; fine on plain sm_100 target).
__device__ __forceinline__ uint32_t smem_addr(const void* p) {
    return (uint32_t)__cvta_generic_to_shared(p);
}
__device__ __forceinline__ void cpasync16(uint32_t dst, const void* src) {
    asm volatile("cp.async.cg.shared.global [%0], [%1], 16;"
                 :: "r"(dst), "l"(src) : "memory");
}
#define CP_COMMIT() asm volatile("cp.async.commit_group;" ::: "memory")
#define CP_WAIT0()  asm volatile("cp.async.wait_group 0;" ::: "memory")
#define CP_WAIT1()  asm volatile("cp.async.wait_group 1;" ::: "memory")

// ---------------------------------------------------------------------------
// ALL projections in ONE launch, grid (8, 32, 3):
//   z=0 -> Q fp32 SIMT;  z=1 -> K fp32 SIMT (TRANSPOSED);  z=2 -> V 3xTF32.
// ---------------------------------------------------------------------------
#define PJ_STR 36
#define PROJ_SMEM (4 * 128 * PJ_STR * 4)

__global__ void __launch_bounds__(256, 2)
proj_all(const float* __restrict__ Xq, const float* __restrict__ Xk,
         const float* __restrict__ Xv,
         const float* __restrict__ Wq, const float* __restrict__ Wk,
         const float* __restrict__ Wv,
         const float* __restrict__ bq, const float* __restrict__ bk,
         const float* __restrict__ bv)
{
    extern __shared__ float ps[];
    const int z   = blockIdx.z;
    const int bi  = blockIdx.y * 128;
    const int bj  = blockIdx.x * 128;
    const int tid = threadIdx.x;

    if (z < 2) {
        const float* X    = z ? Xk : Xq;
        const float* W    = z ? Wk : Wq;
        const float* bias = z ? bk : bq;
        float* dst        = z ? g_K : g_Q;

        float* As = ps;
        float* Bs = ps + 8 * 128;

        const int tx = tid & 15;
        const int ty = tid >> 4;
        const int lr = tid >> 1;
        const int lc = (tid & 1) * 4;

        const float* Xp = X + (size_t)(bi + lr) * DD + lc;
        const float* Wp = W + (size_t)(bj + lr) * DD + lc;

        u64cu accp[8][4];
#pragma unroll
        for (int i = 0; i < 8; i++)
#pragma unroll
            for (int p = 0; p < 4; p++) accp[i][p] = 0ULL;

        for (int k0 = 0; k0 < DD; k0 += 8) {
            float4 a4 = *(const float4*)(Xp + k0);
            float4 w4 = *(const float4*)(Wp + k0);
            As[(lc + 0) * 128 + lr] = a4.x; As[(lc + 1) * 128 + lr] = a4.y;
            As[(lc + 2) * 128 + lr] = a4.z; As[(lc + 3) * 128 + lr] = a4.w;
            Bs[(lc + 0) * 128 + lr] = w4.x; Bs[(lc + 1) * 128 + lr] = w4.y;
            Bs[(lc + 2) * 128 + lr] = w4.z; Bs[(lc + 3) * 128 + lr] = w4.w;
            __syncthreads();

#pragma unroll
            for (int k = 0; k < 8; k++) {
                float av[8];
                F4U2 B0, B1;
                *(float4*)&av[0] = *(const float4*)&As[k * 128 + ty * 8];
                *(float4*)&av[4] = *(const float4*)&As[k * 128 + ty * 8 + 4];
                B0.f4 = *(const float4*)&Bs[k * 128 + tx * 8];
                B1.f4 = *(const float4*)&Bs[k * 128 + tx * 8 + 4];
                const u64cu bp0 = B0.u2[0], bp1 = B0.u2[1];
                const u64cu bp2 = B1.u2[0], bp3 = B1.u2[1];
#pragma unroll
                for (int i = 0; i < 8; i++) {
                    const u64cu ai = dup2(av[i]);
                    fma2(accp[i][0], ai, bp0);
                    fma2(accp[i][1], ai, bp1);
                    fma2(accp[i][2], ai, bp2);
                    fma2(accp[i][3], ai, bp3);
                }
            }
            __syncthreads();
        }

        const int b  = (bi + ty * 8) >> 11;
        const int s0 = (bi + ty * 8) & 2047;

        if (z == 0) {
#pragma unroll
            for (int ii = 0; ii < 8; ii++) {
                const int s = s0 + ii;
#pragma unroll
                for (int p = 0; p < 4; p++) {
                    const int j = bj + tx * 8 + 2 * p;
                    const int h = j >> 6;
                    const int d = j & 63;
                    float2 v = up2(accp[ii][p]);
                    v.x += bias[j];
                    v.y += bias[j + 1];
                    *(float2*)&dst[(((size_t)(b * HH + h)) * SS + s) * HD + d] = v;
                }
            }
        } else {
#pragma unroll
            for (int p = 0; p < 4; p++) {
                const int j = bj + tx * 8 + 2 * p;
                float v0[8], v1[8];
#pragma unroll
                for (int ii = 0; ii < 8; ii++) {
                    float2 v = up2(accp[ii][p]);
                    v0[ii] = v.x + bias[j];
                    v1[ii] = v.y + bias[j + 1];
                }
                const int h0 = j >> 6, d0 = j & 63;
                const int h1 = (j + 1) >> 6, d1 = (j + 1) & 63;
                float* p0 = &dst[(((size_t)(b * HH + h0)) * HD + d0) * SS + s0];
                float* p1 = &dst[(((size_t)(b * HH + h1)) * HD + d1) * SS + s0];
                *(float4*)p0       = *(float4*)&v0[0];
                *(float4*)(p0 + 4) = *(float4*)&v0[4];
                *(float4*)p1       = *(float4*)&v1[0];
                *(float4*)(p1 + 4) = *(float4*)&v1[4];
            }
        }
        return;
    }

    // ================= V: 3xTF32 mma.sync (terminal path) ===================
    {
        const float* X    = Xv;
        const float* W    = Wv;
        const float* bias = bv;
        float* dst        = g_V;

        float* sXh = ps;
        float* sXl = ps + 128 * PJ_STR;
        float* sWh = ps + 2 * 128 * PJ_STR;
        float* sWl = ps + 3 * 128 * PJ_STR;

        const int wid  = tid >> 5;
        const int lane = tid & 31;
        const int wm = wid >> 2;
        const int wn = wid & 3;
        const int lr = lane >> 2;
        const int lc = lane & 3;

        float c[4][4][4];
#pragma unroll
        for (int i = 0; i < 4; i++)
#pragma unroll
            for (int j = 0; j < 4; j++)
#pragma unroll
                for (int e = 0; e < 4; e++) c[i][j][e] = 0.0f;

        for (int ch = 0; ch < 32; ch++) {
            const int k0 = ch * 32;
#pragma unroll
            for (int it = 0; it < 4; it++) {
                const int idx = tid + it * 256;
                const int row = idx >> 3;
                const int q   = (idx & 7) * 4;
                float4 xv = *(const float4*)&X[(size_t)(bi + row) * DD + k0 + q];
                float4 wv = *(const float4*)&W[(size_t)(bj + row) * DD + k0 + q];
                float xh[4], xl[4], wh[4], wl[4];
                const float* xs = (const float*)&xv;
                const float* ws = (const float*)&wv;
#pragma unroll
                for (int e = 0; e < 4; e++) {
                    split_tf32(xs[e], xh[e], xl[e]);
                    split_tf32(ws[e], wh[e], wl[e]);
                }
                *(float4*)&sXh[row * PJ_STR + q] = *(float4*)xh;
                *(float4*)&sXl[row * PJ_STR + q] = *(float4*)xl;
                *(float4*)&sWh[row * PJ_STR + q] = *(float4*)wh;
                *(float4*)&sWl[row * PJ_STR + q] = *(float4*)wl;
            }
            __syncthreads();

#pragma unroll
            for (int k8 = 0; k8 < 4; k8++) {
                const int kc = k8 * 8;
                uint32_t bh[4][2], bl[4][2];
#pragma unroll
                for (int nt = 0; nt < 4; nt++) {
                    const int nr = (wn * 32 + nt * 8 + lr) * PJ_STR + kc + lc;
                    bh[nt][0] = __float_as_uint(sWh[nr]);
                    bh[nt][1] = __float_as_uint(sWh[nr + 4]);
                    bl[nt][0] = __float_as_uint(sWl[nr]);
                    bl[nt][1] = __float_as_uint(sWl[nr + 4]);
                }
#pragma unroll
                for (int mt = 0; mt < 4; mt++) {
                    const int ar = (wm * 64 + mt * 16 + lr) * PJ_STR + kc + lc;
                    uint32_t ah[4], al[4];
                    ah[0] = __float_as_uint(sXh[ar]);
                    ah[1] = __float_as_uint(sXh[ar + 8 * PJ_STR]);
                    ah[2] = __float_as_uint(sXh[ar + 4]);
                    ah[3] = __float_as_uint(sXh[ar + 8 * PJ_STR + 4]);
                    al[0] = __float_as_uint(sXl[ar]);
                    al[1] = __float_as_uint(sXl[ar + 8 * PJ_STR]);
                    al[2] = __float_as_uint(sXl[ar + 4]);
                    al[3] = __float_as_uint(sXl[ar + 8 * PJ_STR + 4]);
#pragma unroll
                    for (int nt = 0; nt < 4; nt++) {
                        mma8(c[mt][nt], ah, bh[nt]);
                        mma8(c[mt][nt], ah, bl[nt]);
                        mma8(c[mt][nt], al, bh[nt]);
                    }
                }
            }
            __syncthreads();
        }

        // Epilogue: bias add, PRE-ROUND to tf32 (bit-identical to cvt at use).
#pragma unroll
        for (int mt = 0; mt < 4; mt++) {
            const int i0 = bi + wm * 64 + mt * 16 + lr;
#pragma unroll
            for (int nt = 0; nt < 4; nt++) {
                const int j = bj + wn * 32 + nt * 8 + 2 * lc;
                const float b0 = bias[j], b1 = bias[j + 1];
                const int h = j >> 6;
                const int d = j & 63;
                {
                    const int bb = i0 >> 11, s = i0 & 2047;
                    float2 v;
                    v.x = __uint_as_float(f2tf32(c[mt][nt][0] + b0));
                    v.y = __uint_as_float(f2tf32(c[mt][nt][1] + b1));
                    *(float2*)&dst[(((size_t)(bb * HH + h)) * SS + s) * HD + d] = v;
                }
                {
                    const int i1 = i0 + 8;
                    const int bb = i1 >> 11, s = i1 & 2047;
                    float2 v;
                    v.x = __uint_as_float(f2tf32(c[mt][nt][2] + b0));
                    v.y = __uint_as_float(f2tf32(c[mt][nt][3] + b1));
                    *(float2*)&dst[(((size_t)(bb * HH + h)) * SS + s) * HD + d] = v;
                }
            }
        }
    }
}

// ---------------------------------------------------------------------------
// Fused attention per (b, h, 8-row q-block). 256 threads (8 warps).
// 2 CTAs/SM (104.6 KB smem) -> cross-CTA phase overlap on all pipes.
//   Phase 1: fp32 QK^T, cp.async double-buffered [16][256] d-quarter steps,
//            d=0..63 sequential per output -> bit-exact raw.
//   Phase 2: softmax (warp per row), inv -> smem, attn_mean fused (red.v4).
//   Phase 3: attn @ V tf32 mma (upper 8 M-rows zeroed), warp-private
//            8x72 V slices, cp.async depth-1; partials red.v2 into out.
// SMEM: sc 8x2052 | vstage 9216 (ph1: 2x[16][256]; ph3: 8x2x[8][72]) |
//       qt [64][8] | sinv  = 104,640 B.
// ---------------------------------------------------------------------------
#define SC_STR 2052
#define VSTAGE_FLOATS 9216
#define SMEM_FLOATS (8 * SC_STR + VSTAGE_FLOATS + 512 + 16)
#define SMEM_BYTES  (SMEM_FLOATS * 4)

__global__ void __launch_bounds__(256, 2) attn_kernel(float* __restrict__ out)
{
    extern __shared__ float sm[];
    float* sc     = sm;                        // scores (e), [8][2052]
    float* vstage = sm + 8 * SC_STR;           // staging region
    float* qt     = vstage + VSTAGE_FLOATS;    // Q^T [64][8]
    float* sinv   = qt + 512;                  // [8] row inv factors

    const int cta = blockIdx.x;                // b*4096 + h*256 + qb
    const int qb  = cta & 255;
    const int h   = (cta >> 8) & 15;
    const int b   = cta >> 12;
    const int q0  = qb * 8;
    const int tid = threadIdx.x;
    const int wid  = tid >> 5;
    const int lane = tid & 31;

    const float* Qg = g_Q + ((size_t)(b * HH + h) * SS + q0) * HD;
    const float* Kg = g_K + (size_t)(b * HH + h) * HD * SS;   // [d][s]
    const float* Vg = g_V + (size_t)(b * HH + h) * SS * HD;

    // Load Q tile transposed: qt[d][r], 8 rows x 64 d; float2 per thread.
    {
        const int r  = tid >> 5;               // 0..7
        const int c2 = (tid & 31) * 2;         // 0..62
        float2 v = *(const float2*)&Qg[r * HD + c2];
        qt[(c2 + 0) * 8 + r] = v.x;
        qt[(c2 + 1) * 8 + r] = v.y;
    }

    // ---- Phase 1: raw = Q K^T (fp32, d ascending per output) ----
    const int rg  = tid >> 7;          // 0..1 -> rows rg*4..rg*4+3
    const int cg  = tid & 127;         // cols cg*2, cg*2+1
    const int r0  = rg * 4;
    const int cg2 = cg * 2;

    {
        float* kb0 = vstage;           // [16][256]
        float* kb1 = vstage + 4096;
        const int lf_d = tid >> 6;     // 0..3 (+ i*4)
        const int lf_c = (tid & 63) * 4;
        // prologue: step 0 (kc=0, dq=0)
#pragma unroll
        for (int i = 0; i < 4; i++) {
            const int dl = lf_d + i * 4;
            cpasync16(smem_addr(&kb0[dl * 256 + lf_c]),
                      Kg + (size_t)dl * SS + lf_c);
        }
        CP_COMMIT();

        for (int kc = 0; kc < 8; kc++) {
            u64cu a01c0 = 0ULL, a23c0 = 0ULL, a01c1 = 0ULL, a23c1 = 0ULL;
#pragma unroll
            for (int dq = 0; dq < 4; dq++) {
                const int s = kc * 4 + dq;
                CP_WAIT0();
                __syncthreads();
                if (s < 31) {
                    const int s1  = s + 1;
                    const int kc1 = s1 >> 2, dq1 = s1 & 3;
                    float* db = (s1 & 1) ? kb1 : kb0;
#pragma unroll
                    for (int i = 0; i < 4; i++) {
                        const int dl = lf_d + i * 4;
                        cpasync16(smem_addr(&db[dl * 256 + lf_c]),
                                  Kg + (size_t)(dq1 * 16 + dl) * SS
                                     + kc1 * 256 + lf_c);
                    }
                    CP_COMMIT();
                }
                const float* kb = (s & 1) ? kb1 : kb0;
#pragma unroll 8
                for (int dd = 0; dd < 16; dd++) {
                    const int d = dq * 16 + dd;
                    F4U2 qv;
                    qv.f4 = *(const float4*)&qt[d * 8 + r0];
                    const u64cu q01 = qv.u2[0], q23 = qv.u2[1];
                    float2 kvv = *(const float2*)&kb[dd * 256 + cg2];
                    const u64cu k0d = dup2(kvv.x);
                    const u64cu k1d = dup2(kvv.y);
                    fma2(a01c0, q01, k0d);
                    fma2(a23c0, q23, k0d);
                    fma2(a01c1, q01, k1d);
                    fma2(a23c1, q23, k1d);
                }
            }
            {
                float2 c0lo = up2(a01c0), c0hi = up2(a23c0);
                float2 c1lo = up2(a01c1), c1hi = up2(a23c1);
                float rowv[4][2] = {{c0lo.x, c1lo.x}, {c0lo.y, c1lo.y},
                                    {c0hi.x, c1hi.x}, {c0hi.y, c1hi.y}};
#pragma unroll
                for (int i = 0; i < 4; i++) {
                    float2 sv;
                    sv.x = __fdividef(1.0f, 8.0f * rowv[i][0]);
                    sv.y = __fdividef(1.0f, 8.0f * rowv[i][1]);
                    *(float2*)&sc[(r0 + i) * SC_STR + kc * 256 + cg2] = sv;
                }
            }
        }
    }
    __syncthreads();

    // ---- Phase 2: softmax (store e only) + fused attn_mean ----
    {
        float* row = sc + wid * SC_STR;       // warp wid owns row wid (0..7)
        float m = -3.4e38f;
        for (int k = lane; k < 2048; k += 32) m = fmaxf(m, row[k]);
#pragma unroll
        for (int o = 16; o; o >>= 1) m = fmaxf(m, __shfl_xor_sync(0xffffffffu, m, o));
        float ssum = 0.0f;
        for (int k = lane; k < 2048; k += 32) {
            float e = __expf(row[k] - m);
            row[k] = e;
            ssum += e;
        }
#pragma unroll
        for (int o = 16; o; o >>= 1) ssum += __shfl_xor_sync(0xffffffffu, ssum, o);
        const float inv = __fdividef(1.0f, ssum);
        if (lane == 0) sinv[wid] = inv;

        const float invm = inv * 0.0625f;     // exact: x2^-4
        float* am = out + (size_t)BB * SS * DD
                  + ((size_t)(b * SS + q0 + wid)) * SS;
        for (int k4 = lane * 4; k4 < 2048; k4 += 128) {
            float4 v = *(const float4*)&row[k4];
            float4 vm = make_float4(v.x * invm, v.y * invm,
                                    v.z * invm, v.w * invm);
            asm volatile("red.global.add.v4.f32 [%0], {%1, %2, %3, %4};"
                         :: "l"(am + k4), "f"(vm.x), "f"(vm.y), "f"(vm.z), "f"(vm.w)
                         : "memory");
        }
    }
    __syncthreads();    // sinv visible; sc final; vstage free

    // ---- Phase 3: out += (e*inv) @ V — warp-private pipeline ----
    {
        const int lr = lane >> 2;     // 0..7 == q-row
        const int lc = lane & 3;
        const float inv_r = sinv[lr];

        float* pw = vstage + wid * 1152;   // 2 private buffers of [8][72]

        float c[8][4];
#pragma unroll
        for (int nt = 0; nt < 8; nt++)
#pragma unroll
            for (int e = 0; e < 4; e++) c[nt][e] = 0.0f;

        // prologue: issue slice for step 0 (V rows wid*8..wid*8+7)
        {
#pragma unroll
            for (int i = 0; i < 4; i++) {
                const int ch  = lane + i * 32;     // 0..127
                const int row = ch >> 4;           // 0..7
                const int seg = (ch & 15) * 4;
                cpasync16(smem_addr(&pw[row * 72 + seg]),
                          Vg + (size_t)(wid * 8 + row) * HD + seg);
            }
            CP_COMMIT();
        }

        for (int s = 0; s < 32; s++) {
            if (s < 31) {
                float* db = pw + ((s + 1) & 1) * 576;
#pragma unroll
                for (int i = 0; i < 4; i++) {
                    const int ch  = lane + i * 32;
                    const int row = ch >> 4;
                    const int seg = (ch & 15) * 4;
                    cpasync16(smem_addr(&db[row * 72 + seg]),
                              Vg + (size_t)((s + 1) * 64 + wid * 8 + row) * HD
                                 + seg);
                }
                CP_COMMIT();
                CP_WAIT1();
            } else {
                CP_WAIT0();
            }
            __syncwarp();
            const float* vb = pw + (s & 1) * 576;

            uint32_t a[4];
            const int ac = s * 64 + wid * 8 + lc;
            a[0] = f2tf32(sc[lr * SC_STR + ac] * inv_r);
            a[1] = 0;                                   // rows 8-15 unused
            a[2] = f2tf32(sc[lr * SC_STR + ac + 4] * inv_r);
            a[3] = 0;
#pragma unroll
            for (int nt = 0; nt < 8; nt++) {
                uint32_t bf[2];
                const int n = nt * 8 + lr;
                bf[0] = __float_as_uint(vb[lc * 72 + n]);          // pre-tf32
                bf[1] = __float_as_uint(vb[(lc + 4) * 72 + n]);
                mma8(c[nt], a, bf);
            }
        }

        float* ob = out + ((size_t)(b * SS + q0)) * DD + h * HD;
#pragma unroll
        for (int nt = 0; nt < 8; nt++) {
            const int col = nt * 8 + 2 * lc;
            float* p0 = ob + (size_t)lr * DD + col;
            asm volatile("red.global.add.v2.f32 [%0], {%1, %2};"
                         :: "l"(p0), "f"(c[nt][0]), "f"(c[nt][1]) : "memory");
        }
    }
}

// ---------------------------------------------------------------------------
extern "C" void kernel_launch(void* const* d_in, const int* in_sizes, int n_in,
                              void* d_out, int out_size)
{
    const float* query = (const float*)d_in[0];
    const float* key_  = (const float*)d_in[1];
    const float* value = (const float*)d_in[2];
    const float* Wq    = (const float*)d_in[3];
    const float* bq    = (const float*)d_in[4];
    const float* Wk    = (const float*)d_in[5];
    const float* bk    = (const float*)d_in[6];
    const float* Wv    = (const float*)d_in[7];
    const float* bv    = (const float*)d_in[8];
    float* out = (float*)d_out;

    cudaMemsetAsync(out, 0,
                    (size_t)(BB * SS * DD + (size_t)BB * SS * SS) * sizeof(float));

    cudaFuncSetAttribute(proj_all,
                         cudaFuncAttributeMaxDynamicSharedMemorySize, PROJ_SMEM);
    dim3 pg(DD / 128, (BB * SS) / 128, 3);
    proj_all<<<pg, 256, PROJ_SMEM>>>(query, key_, value, Wq, Wk, Wv, bq, bk, bv);

    cudaFuncSetAttribute(attn_kernel,
                         cudaFuncAttributeMaxDynamicSharedMemorySize, SMEM_BYTES);
    attn_kernel<<<BB * HH * (SS / 8), 256, SMEM_BYTES>>>(out);
}

// round 17
// speedup vs baseline: 1.0780x; 1.0780x over previous
#include <cuda_runtime.h>
#include <cstdint>

#define BB 2
#define SS 2048
#define DD 1024
#define HH 16
#define HD 64

// Scratch: g_Q [b,h][s][64]; g_K TRANSPOSED [b,h][d][s]; g_V [b,h][s][64]
// (V values pre-rounded to tf32 in proj — terminal path, bit-identical out).
__device__ float g_Q[BB*HH*SS*HD];
__device__ float g_K[BB*HH*SS*HD];
__device__ float g_V[BB*HH*SS*HD];

// ---------------------------------------------------------------------------
// Packed f32x2 helpers (exact IEEE fp32 per lane).
// ---------------------------------------------------------------------------
typedef unsigned long long u64cu;
union F4U2 { float4 f4; u64cu u2[2]; };

__device__ __forceinline__ u64cu dup2(float x) {
    u64cu r; asm("mov.b64 %0, {%1, %1};" : "=l"(r) : "f"(x)); return r;
}
__device__ __forceinline__ void fma2(u64cu& c, u64cu a, u64cu b) {
    asm("fma.rn.f32x2 %0, %1, %2, %0;" : "+l"(c) : "l"(a), "l"(b));
}
__device__ __forceinline__ float2 up2(u64cu v) {
    float2 f; asm("mov.b64 {%0, %1}, %2;" : "=f"(f.x), "=f"(f.y) : "l"(v));
    return f;
}

// ---------------------------------------------------------------------------
// tf32 mma.sync helpers (downstream-of-softmax paths only).
// ---------------------------------------------------------------------------
__device__ __forceinline__ uint32_t f2tf32(float x) {
    uint32_t r;
    asm("cvt.rna.tf32.f32 %0, %1;" : "=r"(r) : "f"(x));
    return r;
}
__device__ __forceinline__ void split_tf32(float v, float& hi, float& lo) {
    uint32_t hb;
    asm("cvt.rna.tf32.f32 %0, %1;" : "=r"(hb) : "f"(v));
    hi = __uint_as_float(hb);
    float r = v - hi;
    uint32_t lb;
    asm("cvt.rna.tf32.f32 %0, %1;" : "=r"(lb) : "f"(r));
    lo = __uint_as_float(lb);
}
__device__ __forceinline__ void mma8(float* c, const uint32_t* a, const uint32_t* bf) {
    asm volatile("mma.sync.aligned.m16n8k8.row.col.f32.tf32.tf32.f32 "
                 "{%0,%1,%2,%3}, {%4,%5,%6,%7}, {%8,%9}, {%0,%1,%2,%3};"
                 : "+f"(c[0]), "+f"(c[1]), "+f"(c[2]), "+f"(c[3])
                 : "r"(a[0]), "r"(a[1]), "r"(a[2]), "r"(a[3]),
                   "r"(bf[0]), "r"(bf[1]));
}

// cp.async (Ampere+ PTX; fine on plain sm_100 target).
__device__ __forceinline__ uint32_t smem_addr(const void* p) {
    return (uint32_t)__cvta_generic_to_shared(p);
}
__device__ __forceinline__ void cpasync16(uint32_t dst, const void* src) {
    asm volatile("cp.async.cg.shared.global [%0], [%1], 16;"
                 :: "r"(dst), "l"(src) : "memory");
}
#define CP_COMMIT() asm volatile("cp.async.commit_group;" ::: "memory")
#define CP_WAIT0()  asm volatile("cp.async.wait_group 0;" ::: "memory")
#define CP_WAIT1()  asm volatile("cp.async.wait_group 1;" ::: "memory")
#define NBAR(id, n) asm volatile("bar.sync %0, %1;" :: "r"(id), "r"(n) : "memory")

// ---------------------------------------------------------------------------
// ALL projections in ONE launch, grid (8, 32, 3):
//   z=0 -> Q fp32 SIMT;  z=1 -> K fp32 SIMT (TRANSPOSED);  z=2 -> V 3xTF32.
// ---------------------------------------------------------------------------
#define PJ_STR 36
#define PROJ_SMEM (4 * 128 * PJ_STR * 4)

__global__ void __launch_bounds__(256, 2)
proj_all(const float* __restrict__ Xq, const float* __restrict__ Xk,
         const float* __restrict__ Xv,
         const float* __restrict__ Wq, const float* __restrict__ Wk,
         const float* __restrict__ Wv,
         const float* __restrict__ bq, const float* __restrict__ bk,
         const float* __restrict__ bv)
{
    extern __shared__ float ps[];
    const int z   = blockIdx.z;
    const int bi  = blockIdx.y * 128;
    const int bj  = blockIdx.x * 128;
    const int tid = threadIdx.x;

    if (z < 2) {
        const float* X    = z ? Xk : Xq;
        const float* W    = z ? Wk : Wq;
        const float* bias = z ? bk : bq;
        float* dst        = z ? g_K : g_Q;

        float* As = ps;
        float* Bs = ps + 8 * 128;

        const int tx = tid & 15;
        const int ty = tid >> 4;
        const int lr = tid >> 1;
        const int lc = (tid & 1) * 4;

        const float* Xp = X + (size_t)(bi + lr) * DD + lc;
        const float* Wp = W + (size_t)(bj + lr) * DD + lc;

        u64cu accp[8][4];
#pragma unroll
        for (int i = 0; i < 8; i++)
#pragma unroll
            for (int p = 0; p < 4; p++) accp[i][p] = 0ULL;

        for (int k0 = 0; k0 < DD; k0 += 8) {
            float4 a4 = *(const float4*)(Xp + k0);
            float4 w4 = *(const float4*)(Wp + k0);
            As[(lc + 0) * 128 + lr] = a4.x; As[(lc + 1) * 128 + lr] = a4.y;
            As[(lc + 2) * 128 + lr] = a4.z; As[(lc + 3) * 128 + lr] = a4.w;
            Bs[(lc + 0) * 128 + lr] = w4.x; Bs[(lc + 1) * 128 + lr] = w4.y;
            Bs[(lc + 2) * 128 + lr] = w4.z; Bs[(lc + 3) * 128 + lr] = w4.w;
            __syncthreads();

#pragma unroll
            for (int k = 0; k < 8; k++) {
                float av[8];
                F4U2 B0, B1;
                *(float4*)&av[0] = *(const float4*)&As[k * 128 + ty * 8];
                *(float4*)&av[4] = *(const float4*)&As[k * 128 + ty * 8 + 4];
                B0.f4 = *(const float4*)&Bs[k * 128 + tx * 8];
                B1.f4 = *(const float4*)&Bs[k * 128 + tx * 8 + 4];
                const u64cu bp0 = B0.u2[0], bp1 = B0.u2[1];
                const u64cu bp2 = B1.u2[0], bp3 = B1.u2[1];
#pragma unroll
                for (int i = 0; i < 8; i++) {
                    const u64cu ai = dup2(av[i]);
                    fma2(accp[i][0], ai, bp0);
                    fma2(accp[i][1], ai, bp1);
                    fma2(accp[i][2], ai, bp2);
                    fma2(accp[i][3], ai, bp3);
                }
            }
            __syncthreads();
        }

        const int b  = (bi + ty * 8) >> 11;
        const int s0 = (bi + ty * 8) & 2047;

        if (z == 0) {
#pragma unroll
            for (int ii = 0; ii < 8; ii++) {
                const int s = s0 + ii;
#pragma unroll
                for (int p = 0; p < 4; p++) {
                    const int j = bj + tx * 8 + 2 * p;
                    const int h = j >> 6;
                    const int d = j & 63;
                    float2 v = up2(accp[ii][p]);
                    v.x += bias[j];
                    v.y += bias[j + 1];
                    *(float2*)&dst[(((size_t)(b * HH + h)) * SS + s) * HD + d] = v;
                }
            }
        } else {
#pragma unroll
            for (int p = 0; p < 4; p++) {
                const int j = bj + tx * 8 + 2 * p;
                float v0[8], v1[8];
#pragma unroll
                for (int ii = 0; ii < 8; ii++) {
                    float2 v = up2(accp[ii][p]);
                    v0[ii] = v.x + bias[j];
                    v1[ii] = v.y + bias[j + 1];
                }
                const int h0 = j >> 6, d0 = j & 63;
                const int h1 = (j + 1) >> 6, d1 = (j + 1) & 63;
                float* p0 = &dst[(((size_t)(b * HH + h0)) * HD + d0) * SS + s0];
                float* p1 = &dst[(((size_t)(b * HH + h1)) * HD + d1) * SS + s0];
                *(float4*)p0       = *(float4*)&v0[0];
                *(float4*)(p0 + 4) = *(float4*)&v0[4];
                *(float4*)p1       = *(float4*)&v1[0];
                *(float4*)(p1 + 4) = *(float4*)&v1[4];
            }
        }
        return;
    }

    // ================= V: 3xTF32 mma.sync (terminal path) ===================
    {
        const float* X    = Xv;
        const float* W    = Wv;
        const float* bias = bv;
        float* dst        = g_V;

        float* sXh = ps;
        float* sXl = ps + 128 * PJ_STR;
        float* sWh = ps + 2 * 128 * PJ_STR;
        float* sWl = ps + 3 * 128 * PJ_STR;

        const int wid  = tid >> 5;
        const int lane = tid & 31;
        const int wm = wid >> 2;
        const int wn = wid & 3;
        const int lr = lane >> 2;
        const int lc = lane & 3;

        float c[4][4][4];
#pragma unroll
        for (int i = 0; i < 4; i++)
#pragma unroll
            for (int j = 0; j < 4; j++)
#pragma unroll
                for (int e = 0; e < 4; e++) c[i][j][e] = 0.0f;

        for (int ch = 0; ch < 32; ch++) {
            const int k0 = ch * 32;
#pragma unroll
            for (int it = 0; it < 4; it++) {
                const int idx = tid + it * 256;
                const int row = idx >> 3;
                const int q   = (idx & 7) * 4;
                float4 xv = *(const float4*)&X[(size_t)(bi + row) * DD + k0 + q];
                float4 wv = *(const float4*)&W[(size_t)(bj + row) * DD + k0 + q];
                float xh[4], xl[4], wh[4], wl[4];
                const float* xs = (const float*)&xv;
                const float* ws = (const float*)&wv;
#pragma unroll
                for (int e = 0; e < 4; e++) {
                    split_tf32(xs[e], xh[e], xl[e]);
                    split_tf32(ws[e], wh[e], wl[e]);
                }
                *(float4*)&sXh[row * PJ_STR + q] = *(float4*)xh;
                *(float4*)&sXl[row * PJ_STR + q] = *(float4*)xl;
                *(float4*)&sWh[row * PJ_STR + q] = *(float4*)wh;
                *(float4*)&sWl[row * PJ_STR + q] = *(float4*)wl;
            }
            __syncthreads();

#pragma unroll
            for (int k8 = 0; k8 < 4; k8++) {
                const int kc = k8 * 8;
                uint32_t bh[4][2], bl[4][2];
#pragma unroll
                for (int nt = 0; nt < 4; nt++) {
                    const int nr = (wn * 32 + nt * 8 + lr) * PJ_STR + kc + lc;
                    bh[nt][0] = __float_as_uint(sWh[nr]);
                    bh[nt][1] = __float_as_uint(sWh[nr + 4]);
                    bl[nt][0] = __float_as_uint(sWl[nr]);
                    bl[nt][1] = __float_as_uint(sWl[nr + 4]);
                }
#pragma unroll
                for (int mt = 0; mt < 4; mt++) {
                    const int ar = (wm * 64 + mt * 16 + lr) * PJ_STR + kc + lc;
                    uint32_t ah[4], al[4];
                    ah[0] = __float_as_uint(sXh[ar]);
                    ah[1] = __float_as_uint(sXh[ar + 8 * PJ_STR]);
                    ah[2] = __float_as_uint(sXh[ar + 4]);
                    ah[3] = __float_as_uint(sXh[ar + 8 * PJ_STR + 4]);
                    al[0] = __float_as_uint(sXl[ar]);
                    al[1] = __float_as_uint(sXl[ar + 8 * PJ_STR]);
                    al[2] = __float_as_uint(sXl[ar + 4]);
                    al[3] = __float_as_uint(sXl[ar + 8 * PJ_STR + 4]);
#pragma unroll
                    for (int nt = 0; nt < 4; nt++) {
                        mma8(c[mt][nt], ah, bh[nt]);
                        mma8(c[mt][nt], ah, bl[nt]);
                        mma8(c[mt][nt], al, bh[nt]);
                    }
                }
            }
            __syncthreads();
        }

        // Epilogue: bias add, PRE-ROUND to tf32 (bit-identical to cvt at use).
#pragma unroll
        for (int mt = 0; mt < 4; mt++) {
            const int i0 = bi + wm * 64 + mt * 16 + lr;
#pragma unroll
            for (int nt = 0; nt < 4; nt++) {
                const int j = bj + wn * 32 + nt * 8 + 2 * lc;
                const float b0 = bias[j], b1 = bias[j + 1];
                const int h = j >> 6;
                const int d = j & 63;
                {
                    const int bb = i0 >> 11, s = i0 & 2047;
                    float2 v;
                    v.x = __uint_as_float(f2tf32(c[mt][nt][0] + b0));
                    v.y = __uint_as_float(f2tf32(c[mt][nt][1] + b1));
                    *(float2*)&dst[(((size_t)(bb * HH + h)) * SS + s) * HD + d] = v;
                }
                {
                    const int i1 = i0 + 8;
                    const int bb = i1 >> 11, s = i1 & 2047;
                    float2 v;
                    v.x = __uint_as_float(f2tf32(c[mt][nt][2] + b0));
                    v.y = __uint_as_float(f2tf32(c[mt][nt][3] + b1));
                    *(float2*)&dst[(((size_t)(bb * HH + h)) * SS + s) * HD + d] = v;
                }
            }
        }
    }
}

// ---------------------------------------------------------------------------
// Fused attention per (b, h, 16-row q-block). 512 threads (16 warps).
//   Phase 1: fp32 QK^T; 4 warp-groups {w%4} each own a 64-col quarter with
//            a private double-buffered [32][64] K stage + NAMED barriers
//            (4-warp scope) — same fma chains/order -> bit-exact raw.
//   Phase 2: softmax stores e; inv -> smem; attn_mean fused (red.v4).
//   Phase 3: warp-private 8x72 V slices, cp.async depth-1, no barriers.
// SMEM: sc 16x2052 | stage 18432 (ph1: 4 groups x 2 x [32][64];
//       ph3: 16 x 2 x [8][72]) | qt 1024 | sinv 16  = 209 KB.
// ---------------------------------------------------------------------------
#define SC_STR 2052
#define VBUF_FLOATS 18432
#define SMEM_FLOATS (16 * SC_STR + VBUF_FLOATS + 1024 + 16)
#define SMEM_BYTES  (SMEM_FLOATS * 4)

__global__ void __launch_bounds__(512) attn_kernel(float* __restrict__ out)
{
    extern __shared__ float sm[];
    float* sc   = sm;                          // scores (e), [16][2052]
    float* vbuf = sm + 16 * SC_STR;            // shared staging region
    float* qt   = vbuf + VBUF_FLOATS;          // Q^T [64][16]
    float* sinv = qt + 1024;                   // [16] row inv factors

    const int cta = blockIdx.x;
    const int qb  = cta & 127;
    const int h   = (cta >> 7) & 15;
    const int b   = cta >> 11;
    const int q0  = qb * 16;
    const int tid = threadIdx.x;
    const int wid  = tid >> 5;
    const int lane = tid & 31;

    const float* Qg = g_Q + ((size_t)(b * HH + h) * SS + q0) * HD;
    const float* Kg = g_K + (size_t)(b * HH + h) * HD * SS;   // [d][s]
    const float* Vg = g_V + (size_t)(b * HH + h) * SS * HD;

    if (tid < 256) {
        const int r  = tid >> 4;
        const int c4 = (tid & 15) * 4;
        float4 v = *(const float4*)&Qg[r * HD + c4];
        qt[(c4 + 0) * 16 + r] = v.x;
        qt[(c4 + 1) * 16 + r] = v.y;
        qt[(c4 + 2) * 16 + r] = v.z;
        qt[(c4 + 3) * 16 + r] = v.w;
    }

    // ---- Phase 1: raw = Q K^T (fp32, order-preserving); sc = 1/(8 raw) ----
    const int rg  = tid >> 7;          // 0..3 -> rows rg*4..rg*4+3
    const int r0  = rg * 4;
    const int grp = wid & 3;           // column-quarter group 0..3
    const int gt  = rg * 32 + lane;    // 0..127 thread index within group
    const int cg2 = 2 * (tid & 127);   // global col pair base (= 64*grp + 2*lane*?)

    {
        // group-private double buffers [32][64] at vbuf + grp*4096.
        float* gb0 = vbuf + grp * 4096;
        float* gb1 = gb0 + 2048;
        const int col0 = grp * 64;     // this group's column-quarter offset

        // prologue: step 0 (kc=0, dh=0)
#pragma unroll
        for (int i = 0; i < 4; i++) {
            const int f  = gt + i * 128;       // float4 id 0..511
            const int dl = f >> 4;             // 0..31
            const int c4 = (f & 15) * 4;       // 0..60
            cpasync16(smem_addr(&gb0[dl * 64 + c4]),
                      Kg + (size_t)dl * SS + col0 + c4);
        }
        CP_COMMIT();
        __syncthreads();    // qt visible to ALL warps (also orders prologue)

        for (int kc = 0; kc < 8; kc++) {
            u64cu a01c0 = 0ULL, a23c0 = 0ULL, a01c1 = 0ULL, a23c1 = 0ULL;
#pragma unroll
            for (int dh = 0; dh < 2; dh++) {
                const int s = kc * 2 + dh;
                CP_WAIT0();
                NBAR(1 + grp, 128);            // group-scope barrier
                if (s < 15) {
                    const int s1  = s + 1;
                    const int kc1 = s1 >> 1, dh1 = s1 & 1;
                    float* db = (s1 & 1) ? gb1 : gb0;
#pragma unroll
                    for (int i = 0; i < 4; i++) {
                        const int f  = gt + i * 128;
                        const int dl = f >> 4;
                        const int c4 = (f & 15) * 4;
                        cpasync16(smem_addr(&db[dl * 64 + c4]),
                                  Kg + (size_t)(dh1 * 32 + dl) * SS
                                     + kc1 * 256 + col0 + c4);
                    }
                    CP_COMMIT();
                }
                const float* kb = (s & 1) ? gb1 : gb0;
#pragma unroll 8
                for (int dd = 0; dd < 32; dd++) {
                    const int d = dh * 32 + dd;
                    F4U2 qv;
                    qv.f4 = *(const float4*)&qt[d * 16 + r0];
                    const u64cu q01 = qv.u2[0], q23 = qv.u2[1];
                    float2 kvv = *(const float2*)&kb[dd * 64 + 2 * lane];
                    const u64cu k0d = dup2(kvv.x);
                    const u64cu k1d = dup2(kvv.y);
                    fma2(a01c0, q01, k0d);
                    fma2(a23c0, q23, k0d);
                    fma2(a01c1, q01, k1d);
                    fma2(a23c1, q23, k1d);
                }
            }
            {
                float2 c0lo = up2(a01c0), c0hi = up2(a23c0);
                float2 c1lo = up2(a01c1), c1hi = up2(a23c1);
                float rowv[4][2] = {{c0lo.x, c1lo.x}, {c0lo.y, c1lo.y},
                                    {c0hi.x, c1hi.x}, {c0hi.y, c1hi.y}};
#pragma unroll
                for (int i = 0; i < 4; i++) {
                    float2 sv;
                    sv.x = __fdividef(1.0f, 8.0f * rowv[i][0]);
                    sv.y = __fdividef(1.0f, 8.0f * rowv[i][1]);
                    *(float2*)&sc[(r0 + i) * SC_STR + kc * 256 + cg2] = sv;
                }
            }
        }
    }
    __syncthreads();

    // ---- Phase 2: softmax (store e only) + fused attn_mean ----
    {
        float* row = sc + wid * SC_STR;
        float m = -3.4e38f;
        for (int k = lane; k < 2048; k += 32) m = fmaxf(m, row[k]);
#pragma unroll
        for (int o = 16; o; o >>= 1) m = fmaxf(m, __shfl_xor_sync(0xffffffffu, m, o));
        float ssum = 0.0f;
        for (int k = lane; k < 2048; k += 32) {
            float e = __expf(row[k] - m);
            row[k] = e;
            ssum += e;
        }
#pragma unroll
        for (int o = 16; o; o >>= 1) ssum += __shfl_xor_sync(0xffffffffu, ssum, o);
        const float inv = __fdividef(1.0f, ssum);
        if (lane == 0) sinv[wid] = inv;

        const float invm = inv * 0.0625f;
        float* am = out + (size_t)BB * SS * DD
                  + ((size_t)(b * SS + q0 + wid)) * SS;
        for (int k4 = lane * 4; k4 < 2048; k4 += 128) {
            float4 v = *(const float4*)&row[k4];
            float4 vm = make_float4(v.x * invm, v.y * invm,
                                    v.z * invm, v.w * invm);
            asm volatile("red.global.add.v4.f32 [%0], {%1, %2, %3, %4};"
                         :: "l"(am + k4), "f"(vm.x), "f"(vm.y), "f"(vm.z), "f"(vm.w)
                         : "memory");
        }
    }
    __syncthreads();    // sinv visible to all warps; sc final; vbuf free

    // ---- Phase 3: out += (e*inv) @ V — WARP-PRIVATE pipeline, no barriers --
    {
        const int lr = lane >> 2;
        const int lc = lane & 3;
        const float inv_lo = sinv[lr];
        const float inv_hi = sinv[lr + 8];

        float* pw = vbuf + wid * 1152;     // 2 private buffers of [8][72]

        float c[8][4];
#pragma unroll
        for (int nt = 0; nt < 8; nt++)
#pragma unroll
            for (int e = 0; e < 4; e++) c[nt][e] = 0.0f;

        // prologue: issue slice for step 0 into buffer 0
        {
#pragma unroll
            for (int i = 0; i < 4; i++) {
                const int ch  = lane + i * 32;     // 0..127 chunk id
                const int row = ch >> 4;           // 0..7
                const int seg = (ch & 15) * 4;
                cpasync16(smem_addr(&pw[row * 72 + seg]),
                          Vg + (size_t)(wid * 8 + row) * HD + seg);
            }
            CP_COMMIT();
        }

        for (int s = 0; s < 16; s++) {
            if (s < 15) {
                float* db = pw + ((s + 1) & 1) * 576;
#pragma unroll
                for (int i = 0; i < 4; i++) {
                    const int ch  = lane + i * 32;
                    const int row = ch >> 4;
                    const int seg = (ch & 15) * 4;
                    cpasync16(smem_addr(&db[row * 72 + seg]),
                              Vg + (size_t)((s + 1) * 128 + wid * 8 + row) * HD
                                 + seg);
                }
                CP_COMMIT();
                CP_WAIT1();        // step-s slice complete
            } else {
                CP_WAIT0();
            }
            __syncwarp();
            const float* vb = pw + (s & 1) * 576;

            uint32_t a[4];
            const int ac = s * 128 + wid * 8 + lc;
            a[0] = f2tf32(sc[lr * SC_STR + ac] * inv_lo);
            a[1] = f2tf32(sc[(lr + 8) * SC_STR + ac] * inv_hi);
            a[2] = f2tf32(sc[lr * SC_STR + ac + 4] * inv_lo);
            a[3] = f2tf32(sc[(lr + 8) * SC_STR + ac + 4] * inv_hi);
#pragma unroll
            for (int nt = 0; nt < 8; nt++) {
                uint32_t bf[2];
                const int n = nt * 8 + lr;
                bf[0] = __float_as_uint(vb[lc * 72 + n]);          // pre-tf32
                bf[1] = __float_as_uint(vb[(lc + 4) * 72 + n]);
                mma8(c[nt], a, bf);
            }
        }

        float* ob = out + ((size_t)(b * SS + q0)) * DD + h * HD;
#pragma unroll
        for (int nt = 0; nt < 8; nt++) {
            const int col = nt * 8 + 2 * lc;
            float* p0 = ob + (size_t)lr * DD + col;
            float* p1 = ob + (size_t)(lr + 8) * DD + col;
            asm volatile("red.global.add.v2.f32 [%0], {%1, %2};"
                         :: "l"(p0), "f"(c[nt][0]), "f"(c[nt][1]) : "memory");
            asm volatile("red.global.add.v2.f32 [%0], {%1, %2};"
                         :: "l"(p1), "f"(c[nt][2]), "f"(c[nt][3]) : "memory");
        }
    }
}

// ---------------------------------------------------------------------------
extern "C" void kernel_launch(void* const* d_in, const int* in_sizes, int n_in,
                              void* d_out, int out_size)
{
    const float* query = (const float*)d_in[0];
    const float* key_  = (const float*)d_in[1];
    const float* value = (const float*)d_in[2];
    const float* Wq    = (const float*)d_in[3];
    const float* bq    = (const float*)d_in[4];
    const float* Wk    = (const float*)d_in[5];
    const float* bk    = (const float*)d_in[6];
    const float* Wv    = (const float*)d_in[7];
    const float* bv    = (const float*)d_in[8];
    float* out = (float*)d_out;

    cudaMemsetAsync(out, 0,
                    (size_t)(BB * SS * DD + (size_t)BB * SS * SS) * sizeof(float));

    cudaFuncSetAttribute(proj_all,
                         cudaFuncAttributeMaxDynamicSharedMemorySize, PROJ_SMEM);
    dim3 pg(DD / 128, (BB * SS) / 128, 3);
    proj_all<<<pg, 256, PROJ_SMEM>>>(query, key_, value, Wq, Wk, Wv, bq, bk, bv);

    cudaFuncSetAttribute(attn_kernel,
                         cudaFuncAttributeMaxDynamicSharedMemorySize, SMEM_BYTES);
    attn_kernel<<<BB * HH * (SS / 16), 512, SMEM_BYTES>>>(out);
}